// round 4
// baseline (speedup 1.0000x reference)
#include <cuda_runtime.h>
#include <math.h>

// Problem constants
#define SQ   2048
#define DM   1024
#define NH   16
#define DH   64
#define BT   2
#define NTOK (BT*SQ)      // 4096
#define DMLP 4096

// ---------------- scratch (device globals; no allocations allowed) ----------
__device__ float g_xln [NTOK*DM];
__device__ float g_q   [NTOK*DM];      // [B,H,S,DH]
__device__ float g_k   [NTOK*DM];
__device__ float g_v   [NTOK*DM];
__device__ float g_z   [NTOK*DM];      // attn concat [tok, h*64+dh]
__device__ float g_rmid[NTOK*DM];
__device__ float g_h2  [NTOK*DM];
__device__ float g_act [NTOK*DMLP];
__device__ float g_wq  [DM*DM];        // repacked [d, h*64+k]
__device__ float g_wk  [DM*DM];
__device__ float g_wv  [DM*DM];

// ---------------- weight repack: [h,d,k] -> [d, h*64+k] ---------------------
__global__ void repack_kernel(const float* __restrict__ wq,
                              const float* __restrict__ wk,
                              const float* __restrict__ wv) {
    int idx = blockIdx.x * 256 + threadIdx.x;    // 0 .. 1M-1 (out index)
    int d  = idx >> 10;
    int n  = idx & 1023;
    int h  = n >> 6;
    int kk = n & 63;
    int src = h * (DM * DH) + d * DH + kk;
    g_wq[idx] = wq[src];
    g_wk[idx] = wk[src];
    g_wv[idx] = wv[src];
}

// ---------------- layernorm: one block per row (1024 elems, 256 thr) --------
__global__ void ln_kernel(const float* __restrict__ x, const float* __restrict__ w,
                          const float* __restrict__ b, float* __restrict__ y) {
    int row = blockIdx.x;
    int t = threadIdx.x;
    const float4 xv = *(const float4*)(x + (size_t)row * DM + t * 4);
    float s  = xv.x + xv.y + xv.z + xv.w;
    float ss = xv.x*xv.x + xv.y*xv.y + xv.z*xv.z + xv.w*xv.w;
    #pragma unroll
    for (int o = 16; o; o >>= 1) {
        s  += __shfl_xor_sync(0xffffffffu, s,  o);
        ss += __shfl_xor_sync(0xffffffffu, ss, o);
    }
    __shared__ float sb[8], sb2[8];
    int wid = t >> 5, lane = t & 31;
    if (lane == 0) { sb[wid] = s; sb2[wid] = ss; }
    __syncthreads();
    if (wid == 0) {
        s  = sb[lane & 7];
        ss = sb2[lane & 7];
        #pragma unroll
        for (int o = 4; o; o >>= 1) {
            s  += __shfl_xor_sync(0xffffffffu, s,  o);
            ss += __shfl_xor_sync(0xffffffffu, ss, o);
        }
        if (lane == 0) { sb[0] = s; sb2[0] = ss; }
    }
    __syncthreads();
    float mean = sb[0] * (1.0f / DM);
    float var  = sb2[0] * (1.0f / DM) - mean * mean;
    float rstd = rsqrtf(var + 1e-5f);
    float4 wv4 = *(const float4*)(w + t * 4);
    float4 bv4 = *(const float4*)(b + t * 4);
    float4 o4;
    o4.x = (xv.x - mean) * rstd * wv4.x + bv4.x;
    o4.y = (xv.y - mean) * rstd * wv4.y + bv4.y;
    o4.z = (xv.z - mean) * rstd * wv4.z + bv4.z;
    o4.w = (xv.w - mean) * rstd * wv4.w + bv4.w;
    *(float4*)(y + (size_t)row * DM + t * 4) = o4;
}

// ---------------- SGEMM 128x128x8, 256 thr, 8x8/thread ----------------------
// MODE 0: C = A*B + bias                (row-major [M,N])
// MODE 1: scatter to [b,h,s,dh] QKV layout, + bias
// MODE 2: C = A*B + bias + R            (residual add)
// MODE 3: C = relu(A*B + bias)
template <int MODE>
__global__ __launch_bounds__(256)
void sgemm_kernel(const float* __restrict__ A, const float* __restrict__ B,
                  const float* __restrict__ bias, const float* __restrict__ R,
                  float* __restrict__ C, int M, int N, int K) {
    __shared__ float As[8][128];
    __shared__ float Bs[8][128];
    int tid = threadIdx.x;
    int m0 = blockIdx.y * 128, n0 = blockIdx.x * 128;
    int tn = tid & 15, tm = tid >> 4;
    int arow = tid >> 1, ak = (tid & 1) * 4;
    int brow = tid >> 5, bcol = (tid & 31) * 4;
    const float* Ap = A + (size_t)(m0 + arow) * K + ak;
    const float* Bp = B + (size_t)brow * N + n0 + bcol;

    float acc[8][8];
    #pragma unroll
    for (int i = 0; i < 8; i++)
        #pragma unroll
        for (int j = 0; j < 8; j++) acc[i][j] = 0.0f;

    for (int k0 = 0; k0 < K; k0 += 8) {
        float4 a  = *(const float4*)(Ap + k0);
        float4 bv = *(const float4*)(Bp + (size_t)k0 * N);
        As[ak + 0][arow] = a.x;
        As[ak + 1][arow] = a.y;
        As[ak + 2][arow] = a.z;
        As[ak + 3][arow] = a.w;
        *(float4*)&Bs[brow][bcol] = bv;
        __syncthreads();
        #pragma unroll
        for (int kk = 0; kk < 8; kk++) {
            float4 a0 = *(float4*)&As[kk][tm * 8];
            float4 a1 = *(float4*)&As[kk][tm * 8 + 4];
            float4 b0 = *(float4*)&Bs[kk][tn * 8];
            float4 b1 = *(float4*)&Bs[kk][tn * 8 + 4];
            float av[8] = {a0.x, a0.y, a0.z, a0.w, a1.x, a1.y, a1.z, a1.w};
            float bw[8] = {b0.x, b0.y, b0.z, b0.w, b1.x, b1.y, b1.z, b1.w};
            #pragma unroll
            for (int i = 0; i < 8; i++)
                #pragma unroll
                for (int j = 0; j < 8; j++)
                    acc[i][j] = fmaf(av[i], bw[j], acc[i][j]);
        }
        __syncthreads();
    }

    #pragma unroll
    for (int i = 0; i < 8; i++) {
        int m = m0 + tm * 8 + i;
        #pragma unroll
        for (int j = 0; j < 8; j++) {
            int n = n0 + tn * 8 + j;
            float val = acc[i][j] + bias[n];
            if (MODE == 0) {
                C[(size_t)m * N + n] = val;
            } else if (MODE == 1) {
                int bb = m >> 11;          // m / SQ
                int s  = m & (SQ - 1);
                int h  = n >> 6;
                int dk = n & 63;
                C[(((size_t)(bb * NH + h)) * SQ + s) * DH + dk] = val;
            } else if (MODE == 2) {
                C[(size_t)m * N + n] = val + R[(size_t)m * N + n];
            } else { // MODE 3
                C[(size_t)m * N + n] = fmaxf(val, 0.0f);
            }
        }
    }
}

// ---------------- flash attention (fp32), 64x64 Q tile, causal --------------
// q,k,v: [B,H,S,DH]; z out: [tok, h*64+dh]
__global__ __launch_bounds__(256)
void flash_kernel(const float* __restrict__ q, const float* __restrict__ k,
                  const float* __restrict__ v, float* __restrict__ z) {
    extern __shared__ float sm[];
    float* Qs = sm;                 // 64*65
    float* Ks = Qs + 64 * 65;
    float* Vs = Ks + 64 * 65;
    float* Ps = Vs + 64 * 65;

    int qt = blockIdx.x, bh = blockIdx.y;
    int bb = bh >> 4, hh = bh & 15;
    int tid = threadIdx.x, tx = tid & 15, ty = tid >> 4;

    const float* qbase = q + ((size_t)bh * SQ + qt * 64) * DH;
    const float* kbase = k + (size_t)bh * SQ * DH;
    const float* vbase = v + (size_t)bh * SQ * DH;

    int lr = tid >> 4;           // 0..15 (row group)
    int lc = (tid & 15) * 4;     // float4 col
    #pragma unroll
    for (int i = 0; i < 4; i++) {
        int r = lr + i * 16;
        float4 t4 = *(const float4*)(qbase + r * DH + lc);
        Qs[r * 65 + lc + 0] = t4.x; Qs[r * 65 + lc + 1] = t4.y;
        Qs[r * 65 + lc + 2] = t4.z; Qs[r * 65 + lc + 3] = t4.w;
    }

    float mi[4], li[4], acc[4][4];
    #pragma unroll
    for (int i = 0; i < 4; i++) {
        mi[i] = -1e30f; li[i] = 0.0f;
        #pragma unroll
        for (int j = 0; j < 4; j++) acc[i][j] = 0.0f;
    }

    for (int kt = 0; kt <= qt; kt++) {
        __syncthreads();  // guard smem reuse from previous iteration (and Q load)
        #pragma unroll
        for (int i = 0; i < 4; i++) {
            int r = lr + i * 16;
            float4 kk4 = *(const float4*)(kbase + (size_t)(kt * 64 + r) * DH + lc);
            Ks[r * 65 + lc + 0] = kk4.x; Ks[r * 65 + lc + 1] = kk4.y;
            Ks[r * 65 + lc + 2] = kk4.z; Ks[r * 65 + lc + 3] = kk4.w;
            float4 vv4 = *(const float4*)(vbase + (size_t)(kt * 64 + r) * DH + lc);
            Vs[r * 65 + lc + 0] = vv4.x; Vs[r * 65 + lc + 1] = vv4.y;
            Vs[r * 65 + lc + 2] = vv4.z; Vs[r * 65 + lc + 3] = vv4.w;
        }
        __syncthreads();

        // scores 4x4 per thread
        float s[4][4];
        #pragma unroll
        for (int i = 0; i < 4; i++)
            #pragma unroll
            for (int j = 0; j < 4; j++) s[i][j] = 0.0f;
        #pragma unroll 8
        for (int d = 0; d < 64; d++) {
            float a0 = Qs[(ty * 4 + 0) * 65 + d];
            float a1 = Qs[(ty * 4 + 1) * 65 + d];
            float a2 = Qs[(ty * 4 + 2) * 65 + d];
            float a3 = Qs[(ty * 4 + 3) * 65 + d];
            float c0 = Ks[(tx * 4 + 0) * 65 + d];
            float c1 = Ks[(tx * 4 + 1) * 65 + d];
            float c2 = Ks[(tx * 4 + 2) * 65 + d];
            float c3 = Ks[(tx * 4 + 3) * 65 + d];
            s[0][0] = fmaf(a0, c0, s[0][0]); s[0][1] = fmaf(a0, c1, s[0][1]);
            s[0][2] = fmaf(a0, c2, s[0][2]); s[0][3] = fmaf(a0, c3, s[0][3]);
            s[1][0] = fmaf(a1, c0, s[1][0]); s[1][1] = fmaf(a1, c1, s[1][1]);
            s[1][2] = fmaf(a1, c2, s[1][2]); s[1][3] = fmaf(a1, c3, s[1][3]);
            s[2][0] = fmaf(a2, c0, s[2][0]); s[2][1] = fmaf(a2, c1, s[2][1]);
            s[2][2] = fmaf(a2, c2, s[2][2]); s[2][3] = fmaf(a2, c3, s[2][3]);
            s[3][0] = fmaf(a3, c0, s[3][0]); s[3][1] = fmaf(a3, c1, s[3][1]);
            s[3][2] = fmaf(a3, c2, s[3][2]); s[3][3] = fmaf(a3, c3, s[3][3]);
        }
        #pragma unroll
        for (int i = 0; i < 4; i++)
            #pragma unroll
            for (int j = 0; j < 4; j++) s[i][j] *= 0.125f;   // 1/sqrt(64)

        if (kt == qt) {  // causal mask on diagonal tile
            #pragma unroll
            for (int i = 0; i < 4; i++)
                #pragma unroll
                for (int j = 0; j < 4; j++)
                    if (tx * 4 + j > ty * 4 + i) s[i][j] = -1e30f;
        }

        // online softmax
        float al[4], rs[4];
        #pragma unroll
        for (int i = 0; i < 4; i++) {
            float rm = fmaxf(fmaxf(s[i][0], s[i][1]), fmaxf(s[i][2], s[i][3]));
            #pragma unroll
            for (int o = 1; o < 16; o <<= 1)
                rm = fmaxf(rm, __shfl_xor_sync(0xffffffffu, rm, o, 16));
            float mn = fmaxf(mi[i], rm);
            al[i] = __expf(mi[i] - mn);
            mi[i] = mn;
            float r = 0.0f;
            #pragma unroll
            for (int j = 0; j < 4; j++) {
                float p = __expf(s[i][j] - mn);
                s[i][j] = p;
                r += p;
            }
            #pragma unroll
            for (int o = 1; o < 16; o <<= 1)
                r += __shfl_xor_sync(0xffffffffu, r, o, 16);
            rs[i] = r;
            li[i] = li[i] * al[i] + rs[i];
        }

        // stage P to smem
        #pragma unroll
        for (int i = 0; i < 4; i++)
            #pragma unroll
            for (int j = 0; j < 4; j++)
                Ps[(ty * 4 + i) * 65 + tx * 4 + j] = s[i][j];

        #pragma unroll
        for (int i = 0; i < 4; i++)
            #pragma unroll
            for (int j = 0; j < 4; j++) acc[i][j] *= al[i];

        __syncthreads();

        // O += P @ V
        #pragma unroll 8
        for (int n = 0; n < 64; n++) {
            float p0 = Ps[(ty * 4 + 0) * 65 + n];
            float p1 = Ps[(ty * 4 + 1) * 65 + n];
            float p2 = Ps[(ty * 4 + 2) * 65 + n];
            float p3 = Ps[(ty * 4 + 3) * 65 + n];
            float w0 = Vs[n * 65 + tx * 4 + 0];
            float w1 = Vs[n * 65 + tx * 4 + 1];
            float w2 = Vs[n * 65 + tx * 4 + 2];
            float w3 = Vs[n * 65 + tx * 4 + 3];
            acc[0][0] = fmaf(p0, w0, acc[0][0]); acc[0][1] = fmaf(p0, w1, acc[0][1]);
            acc[0][2] = fmaf(p0, w2, acc[0][2]); acc[0][3] = fmaf(p0, w3, acc[0][3]);
            acc[1][0] = fmaf(p1, w0, acc[1][0]); acc[1][1] = fmaf(p1, w1, acc[1][1]);
            acc[1][2] = fmaf(p1, w2, acc[1][2]); acc[1][3] = fmaf(p1, w3, acc[1][3]);
            acc[2][0] = fmaf(p2, w0, acc[2][0]); acc[2][1] = fmaf(p2, w1, acc[2][1]);
            acc[2][2] = fmaf(p2, w2, acc[2][2]); acc[2][3] = fmaf(p2, w3, acc[2][3]);
            acc[3][0] = fmaf(p3, w0, acc[3][0]); acc[3][1] = fmaf(p3, w1, acc[3][1]);
            acc[3][2] = fmaf(p3, w2, acc[3][2]); acc[3][3] = fmaf(p3, w3, acc[3][3]);
        }
    }

    // write z [tok, h*64+dh]
    float* zb = z + ((size_t)bb * SQ + qt * 64) * DM + hh * DH;
    #pragma unroll
    for (int i = 0; i < 4; i++) {
        float inv = 1.0f / li[i];
        #pragma unroll
        for (int j = 0; j < 4; j++)
            zb[(size_t)(ty * 4 + i) * DM + tx * 4 + j] = acc[i][j] * inv;
    }
}

// ---------------- host launcher ---------------------------------------------
static float* sym_addr(const void* symbol) {
    void* p = nullptr;
    cudaGetSymbolAddress(&p, symbol);
    return (float*)p;
}

extern "C" void kernel_launch(void* const* d_in, const int* in_sizes, int n_in,
                              void* d_out, int out_size) {
    const float* resid_pre = (const float*)d_in[0];
    const float* ln1_w = (const float*)d_in[1];
    const float* ln1_b = (const float*)d_in[2];
    const float* W_Q   = (const float*)d_in[3];
    const float* b_Q   = (const float*)d_in[4];
    const float* W_K   = (const float*)d_in[5];
    const float* b_K   = (const float*)d_in[6];
    const float* W_V   = (const float*)d_in[7];
    const float* b_V   = (const float*)d_in[8];
    const float* W_O   = (const float*)d_in[9];
    const float* b_O   = (const float*)d_in[10];
    const float* ln2_w = (const float*)d_in[11];
    const float* ln2_b = (const float*)d_in[12];
    const float* W_in  = (const float*)d_in[13];
    const float* b_in  = (const float*)d_in[14];
    const float* W_out = (const float*)d_in[15];
    const float* b_out = (const float*)d_in[16];
    float* out = (float*)d_out;

    float* xln  = sym_addr(g_xln);
    float* qb   = sym_addr(g_q);
    float* kb   = sym_addr(g_k);
    float* vb   = sym_addr(g_v);
    float* zb   = sym_addr(g_z);
    float* rmid = sym_addr(g_rmid);
    float* h2   = sym_addr(g_h2);
    float* act  = sym_addr(g_act);
    float* wq   = sym_addr(g_wq);
    float* wk   = sym_addr(g_wk);
    float* wv   = sym_addr(g_wv);

    // 1. repack QKV weights
    repack_kernel<<<(DM * DM) / 256, 256>>>(W_Q, W_K, W_V);

    // 2. LN1
    ln_kernel<<<NTOK, 256>>>(resid_pre, ln1_w, ln1_b, xln);

    // 3. QKV projections (scatter epilogue into [b,h,s,dh])
    dim3 gq(DM / 128, NTOK / 128);
    sgemm_kernel<1><<<gq, 256>>>(xln, wq, b_Q, nullptr, qb, NTOK, DM, DM);
    sgemm_kernel<1><<<gq, 256>>>(xln, wk, b_K, nullptr, kb, NTOK, DM, DM);
    sgemm_kernel<1><<<gq, 256>>>(xln, wv, b_V, nullptr, vb, NTOK, DM, DM);

    // 4. flash attention
    static const size_t fl_smem = 4 * 64 * 65 * sizeof(float);  // 66560
    cudaFuncSetAttribute(flash_kernel,
                         cudaFuncAttributeMaxDynamicSharedMemorySize, (int)fl_smem);
    flash_kernel<<<dim3(SQ / 64, BT * NH), 256, fl_smem>>>(qb, kb, vb, zb);

    // 5. O-proj + residual -> resid_mid
    sgemm_kernel<2><<<gq, 256>>>(zb, W_O, b_O, resid_pre, rmid, NTOK, DM, DM);

    // 6. LN2
    ln_kernel<<<NTOK, 256>>>(rmid, ln2_w, ln2_b, h2);

    // 7. MLP in + ReLU
    dim3 gi(DMLP / 128, NTOK / 128);
    sgemm_kernel<3><<<gi, 256>>>(h2, W_in, b_in, nullptr, act, NTOK, DMLP, DM);

    // 8. MLP out + bias + residual -> output
    sgemm_kernel<2><<<gq, 256>>>(act, W_out, b_out, rmid, out, NTOK, DM, DMLP);
}

// round 8
// speedup vs baseline: 2.0104x; 2.0104x over previous
#include <cuda_runtime.h>
#include <cuda_bf16.h>
#include <stdint.h>
#include <cstdint>
#include <math.h>

// Problem constants
#define SQ   2048
#define DM   1024
#define NH   16
#define DH   64
#define BT   2
#define NTOK (BT*SQ)      // 4096
#define DMLP 4096

// ---------------- scratch (device globals; no allocations allowed) ----------
__device__ float g_xln [NTOK*DM];
__device__ float g_q   [NTOK*DM];      // [B,H,S,DH]
__device__ float g_k   [NTOK*DM];
__device__ float g_v   [NTOK*DM];
__device__ float g_z   [NTOK*DM];      // attn concat [tok, h*64+dh]
__device__ float g_rmid[NTOK*DM];
__device__ float g_h2  [NTOK*DM];
__device__ float g_act [NTOK*DMLP];
__device__ float g_wq  [DM*DM];        // repacked [d, h*64+k]
__device__ float g_wk  [DM*DM];
__device__ float g_wv  [DM*DM];

// ---------------- weight repack: [h,d,k] -> [d, h*64+k] ---------------------
__global__ void repack_kernel(const float* __restrict__ wq,
                              const float* __restrict__ wk,
                              const float* __restrict__ wv) {
    int idx = blockIdx.x * 256 + threadIdx.x;
    int d  = idx >> 10;
    int n  = idx & 1023;
    int h  = n >> 6;
    int kk = n & 63;
    int src = h * (DM * DH) + d * DH + kk;
    g_wq[idx] = wq[src];
    g_wk[idx] = wk[src];
    g_wv[idx] = wv[src];
}

// ---------------- layernorm: one block per row (1024 elems, 256 thr) --------
__global__ void ln_kernel(const float* __restrict__ x, const float* __restrict__ w,
                          const float* __restrict__ b, float* __restrict__ y) {
    int row = blockIdx.x;
    int t = threadIdx.x;
    const float4 xv = *(const float4*)(x + (size_t)row * DM + t * 4);
    float s  = xv.x + xv.y + xv.z + xv.w;
    float ss = xv.x*xv.x + xv.y*xv.y + xv.z*xv.z + xv.w*xv.w;
    #pragma unroll
    for (int o = 16; o; o >>= 1) {
        s  += __shfl_xor_sync(0xffffffffu, s,  o);
        ss += __shfl_xor_sync(0xffffffffu, ss, o);
    }
    __shared__ float sb[8], sb2[8];
    int wid = t >> 5, lane = t & 31;
    if (lane == 0) { sb[wid] = s; sb2[wid] = ss; }
    __syncthreads();
    if (wid == 0) {
        s  = sb[lane & 7];
        ss = sb2[lane & 7];
        #pragma unroll
        for (int o = 4; o; o >>= 1) {
            s  += __shfl_xor_sync(0xffffffffu, s,  o);
            ss += __shfl_xor_sync(0xffffffffu, ss, o);
        }
        if (lane == 0) { sb[0] = s; sb2[0] = ss; }
    }
    __syncthreads();
    float mean = sb[0] * (1.0f / DM);
    float var  = sb2[0] * (1.0f / DM) - mean * mean;
    float rstd = rsqrtf(var + 1e-5f);
    float4 wv4 = *(const float4*)(w + t * 4);
    float4 bv4 = *(const float4*)(b + t * 4);
    float4 o4;
    o4.x = (xv.x - mean) * rstd * wv4.x + bv4.x;
    o4.y = (xv.y - mean) * rstd * wv4.y + bv4.y;
    o4.z = (xv.z - mean) * rstd * wv4.z + bv4.z;
    o4.w = (xv.w - mean) * rstd * wv4.w + bv4.w;
    *(float4*)(y + (size_t)row * DM + t * 4) = o4;
}

// ---------------- tensor-core GEMM: bf16 hi/lo split, m16n8k16 mma ----------
// C = A*B (+bias, epilogue by MODE), A fp32 [M,K] row-major, B fp32 [K,N] row-major.
// Split: a = a_hi + a_lo (bf16), acc = ah*bh + ah*bl + al*bh (fp32). Error ~2^-18.
// CTA tile 128x128x32, 8 warps (2x4), warp tile 64x32.
// MODE 0: C = A*B + bias
// MODE 1: scatter to [b,h,s,dh] QKV layout, + bias
// MODE 2: C = A*B + bias + R
// MODE 3: C = relu(A*B + bias)

__device__ __forceinline__ uint32_t smem_u32(const void* p) {
    return (uint32_t)__cvta_generic_to_shared(p);
}

#define LDSM_X4(r0,r1,r2,r3,addr) \
    asm volatile("ldmatrix.sync.aligned.m8n8.x4.shared.b16 {%0,%1,%2,%3}, [%4];" \
        : "=r"(r0),"=r"(r1),"=r"(r2),"=r"(r3) : "r"(addr))

#define LDSM_X4_T(r0,r1,r2,r3,addr) \
    asm volatile("ldmatrix.sync.aligned.m8n8.x4.trans.shared.b16 {%0,%1,%2,%3}, [%4];" \
        : "=r"(r0),"=r"(r1),"=r"(r2),"=r"(r3) : "r"(addr))

#define MMA16816(c, a0,a1,a2,a3, b0,b1) \
    asm volatile("mma.sync.aligned.m16n8k16.row.col.f32.bf16.bf16.f32 " \
        "{%0,%1,%2,%3}, {%4,%5,%6,%7}, {%8,%9}, {%0,%1,%2,%3};" \
        : "+f"(c[0]),"+f"(c[1]),"+f"(c[2]),"+f"(c[3]) \
        : "r"(a0),"r"(a1),"r"(a2),"r"(a3), "r"(b0),"r"(b1))

#define APAD 40
#define BPAD 136

template <int MODE>
__global__ __launch_bounds__(256, 2)
void hgemm_kernel(const float* __restrict__ A, const float* __restrict__ B,
                  const float* __restrict__ bias, const float* __restrict__ R,
                  float* __restrict__ C, int M, int N, int K) {
    __shared__ __align__(16) __nv_bfloat16 As[2][128][APAD];   // [hi/lo][m][k]
    __shared__ __align__(16) __nv_bfloat16 Bs[2][32][BPAD];    // [hi/lo][k][n]

    int tid = threadIdx.x;
    int lane = tid & 31;
    int warp = tid >> 5;
    int wm = warp >> 2;        // 0..1
    int wn = warp & 3;         // 0..3
    int m0 = blockIdx.y * 128, n0 = blockIdx.x * 128;

    // gmem staging assignments
    int ar = tid >> 3;         // 0..31  (A row base)
    int ac = (tid & 7) * 4;    // A k-col (float4)
    int br = tid >> 5;         // 0..7   (B k-row base)
    int bc = (tid & 31) * 4;   // B n-col (float4)

    float acc[4][4][4];
    #pragma unroll
    for (int i = 0; i < 4; i++)
        #pragma unroll
        for (int j = 0; j < 4; j++)
            #pragma unroll
            for (int c = 0; c < 4; c++) acc[i][j][c] = 0.0f;

    // ldmatrix smem addresses (constant over k-loop except ks offset)
    uint32_t a_base_hi = smem_u32(&As[0][wm*64 + (lane & 15)][(lane >> 4) * 8]);
    uint32_t a_base_lo = smem_u32(&As[1][wm*64 + (lane & 15)][(lane >> 4) * 8]);
    uint32_t b_base_hi = smem_u32(&Bs[0][lane & 15][wn*32 + (lane >> 4) * 8]);
    uint32_t b_base_lo = smem_u32(&Bs[1][lane & 15][wn*32 + (lane >> 4) * 8]);

    for (int k0 = 0; k0 < K; k0 += 32) {
        // ---- stage A tile (128x32) fp32 -> bf16 hi/lo smem ----
        #pragma unroll
        for (int q = 0; q < 4; q++) {
            int r = ar + q * 32;
            const float4 av = *(const float4*)(A + (size_t)(m0 + r) * K + k0 + ac);
            float f[4] = {av.x, av.y, av.z, av.w};
            #pragma unroll
            for (int e = 0; e < 4; e++) {
                __nv_bfloat16 h = __float2bfloat16(f[e]);
                As[0][r][ac + e] = h;
                As[1][r][ac + e] = __float2bfloat16(f[e] - __bfloat162float(h));
            }
        }
        // ---- stage B tile (32x128) ----
        #pragma unroll
        for (int q = 0; q < 4; q++) {
            int r = br + q * 8;
            const float4 bv = *(const float4*)(B + (size_t)(k0 + r) * N + n0 + bc);
            float f[4] = {bv.x, bv.y, bv.z, bv.w};
            #pragma unroll
            for (int e = 0; e < 4; e++) {
                __nv_bfloat16 h = __float2bfloat16(f[e]);
                Bs[0][r][bc + e] = h;
                Bs[1][r][bc + e] = __float2bfloat16(f[e] - __bfloat162float(h));
            }
        }
        __syncthreads();

        #pragma unroll
        for (int ks = 0; ks < 2; ks++) {
            // B fragments: 4 n8-tiles, hi and lo
            uint32_t bh[8], bl[8];
            {
                uint32_t off = (uint32_t)(ks * 16 * BPAD * 2);       // k offset in bytes
                LDSM_X4_T(bh[0], bh[1], bh[2], bh[3], b_base_hi + off);
                LDSM_X4_T(bh[4], bh[5], bh[6], bh[7], b_base_hi + off + 16 * 2);
                LDSM_X4_T(bl[0], bl[1], bl[2], bl[3], b_base_lo + off);
                LDSM_X4_T(bl[4], bl[5], bl[6], bl[7], b_base_lo + off + 16 * 2);
            }
            #pragma unroll
            for (int i = 0; i < 4; i++) {
                uint32_t ah0, ah1, ah2, ah3, al0, al1, al2, al3;
                uint32_t aoff = (uint32_t)((i * 16 * APAD + ks * 16) * 2);
                LDSM_X4(ah0, ah1, ah2, ah3, a_base_hi + aoff);
                LDSM_X4(al0, al1, al2, al3, a_base_lo + aoff);
                #pragma unroll
                for (int j = 0; j < 4; j++) {
                    MMA16816(acc[i][j], ah0, ah1, ah2, ah3, bh[2*j], bh[2*j+1]);
                    MMA16816(acc[i][j], ah0, ah1, ah2, ah3, bl[2*j], bl[2*j+1]);
                    MMA16816(acc[i][j], al0, al1, al2, al3, bh[2*j], bh[2*j+1]);
                }
            }
        }
        __syncthreads();
    }

    // ---- epilogue ----
    int gid = lane >> 2;       // 0..7 row within 8
    int tid4 = lane & 3;       // col pair
    #pragma unroll
    for (int i = 0; i < 4; i++) {
        #pragma unroll
        for (int j = 0; j < 4; j++) {
            #pragma unroll
            for (int c = 0; c < 4; c++) {
                int m = m0 + wm * 64 + i * 16 + gid + (c >> 1) * 8;
                int n = n0 + wn * 32 + j * 8 + tid4 * 2 + (c & 1);
                float val = acc[i][j][c] + bias[n];
                if (MODE == 0) {
                    C[(size_t)m * N + n] = val;
                } else if (MODE == 1) {
                    int bb = m >> 11;
                    int s  = m & (SQ - 1);
                    int h  = n >> 6;
                    int dk = n & 63;
                    C[(((size_t)(bb * NH + h)) * SQ + s) * DH + dk] = val;
                } else if (MODE == 2) {
                    C[(size_t)m * N + n] = val + R[(size_t)m * N + n];
                } else {
                    C[(size_t)m * N + n] = fmaxf(val, 0.0f);
                }
            }
        }
    }
}

// ---------------- flash attention (fp32), 64x64 Q tile, causal --------------
__global__ __launch_bounds__(256)
void flash_kernel(const float* __restrict__ q, const float* __restrict__ k,
                  const float* __restrict__ v, float* __restrict__ z) {
    extern __shared__ float sm[];
    float* Qs = sm;                 // 64*65
    float* Ks = Qs + 64 * 65;
    float* Vs = Ks + 64 * 65;
    float* Ps = Vs + 64 * 65;

    int qt = blockIdx.x, bh = blockIdx.y;
    int bb = bh >> 4, hh = bh & 15;
    int tid = threadIdx.x, tx = tid & 15, ty = tid >> 4;

    const float* qbase = q + ((size_t)bh * SQ + qt * 64) * DH;
    const float* kbase = k + (size_t)bh * SQ * DH;
    const float* vbase = v + (size_t)bh * SQ * DH;

    int lr = tid >> 4;
    int lc = (tid & 15) * 4;
    #pragma unroll
    for (int i = 0; i < 4; i++) {
        int r = lr + i * 16;
        float4 t4 = *(const float4*)(qbase + r * DH + lc);
        Qs[r * 65 + lc + 0] = t4.x; Qs[r * 65 + lc + 1] = t4.y;
        Qs[r * 65 + lc + 2] = t4.z; Qs[r * 65 + lc + 3] = t4.w;
    }

    float mi[4], li[4], acc[4][4];
    #pragma unroll
    for (int i = 0; i < 4; i++) {
        mi[i] = -1e30f; li[i] = 0.0f;
        #pragma unroll
        for (int j = 0; j < 4; j++) acc[i][j] = 0.0f;
    }

    for (int kt = 0; kt <= qt; kt++) {
        __syncthreads();
        #pragma unroll
        for (int i = 0; i < 4; i++) {
            int r = lr + i * 16;
            float4 kk4 = *(const float4*)(kbase + (size_t)(kt * 64 + r) * DH + lc);
            Ks[r * 65 + lc + 0] = kk4.x; Ks[r * 65 + lc + 1] = kk4.y;
            Ks[r * 65 + lc + 2] = kk4.z; Ks[r * 65 + lc + 3] = kk4.w;
            float4 vv4 = *(const float4*)(vbase + (size_t)(kt * 64 + r) * DH + lc);
            Vs[r * 65 + lc + 0] = vv4.x; Vs[r * 65 + lc + 1] = vv4.y;
            Vs[r * 65 + lc + 2] = vv4.z; Vs[r * 65 + lc + 3] = vv4.w;
        }
        __syncthreads();

        float s[4][4];
        #pragma unroll
        for (int i = 0; i < 4; i++)
            #pragma unroll
            for (int j = 0; j < 4; j++) s[i][j] = 0.0f;
        #pragma unroll 8
        for (int d = 0; d < 64; d++) {
            float a0 = Qs[(ty * 4 + 0) * 65 + d];
            float a1 = Qs[(ty * 4 + 1) * 65 + d];
            float a2 = Qs[(ty * 4 + 2) * 65 + d];
            float a3 = Qs[(ty * 4 + 3) * 65 + d];
            float c0 = Ks[(tx * 4 + 0) * 65 + d];
            float c1 = Ks[(tx * 4 + 1) * 65 + d];
            float c2 = Ks[(tx * 4 + 2) * 65 + d];
            float c3 = Ks[(tx * 4 + 3) * 65 + d];
            s[0][0] = fmaf(a0, c0, s[0][0]); s[0][1] = fmaf(a0, c1, s[0][1]);
            s[0][2] = fmaf(a0, c2, s[0][2]); s[0][3] = fmaf(a0, c3, s[0][3]);
            s[1][0] = fmaf(a1, c0, s[1][0]); s[1][1] = fmaf(a1, c1, s[1][1]);
            s[1][2] = fmaf(a1, c2, s[1][2]); s[1][3] = fmaf(a1, c3, s[1][3]);
            s[2][0] = fmaf(a2, c0, s[2][0]); s[2][1] = fmaf(a2, c1, s[2][1]);
            s[2][2] = fmaf(a2, c2, s[2][2]); s[2][3] = fmaf(a2, c3, s[2][3]);
            s[3][0] = fmaf(a3, c0, s[3][0]); s[3][1] = fmaf(a3, c1, s[3][1]);
            s[3][2] = fmaf(a3, c2, s[3][2]); s[3][3] = fmaf(a3, c3, s[3][3]);
        }
        #pragma unroll
        for (int i = 0; i < 4; i++)
            #pragma unroll
            for (int j = 0; j < 4; j++) s[i][j] *= 0.125f;

        if (kt == qt) {
            #pragma unroll
            for (int i = 0; i < 4; i++)
                #pragma unroll
                for (int j = 0; j < 4; j++)
                    if (tx * 4 + j > ty * 4 + i) s[i][j] = -1e30f;
        }

        float al[4], rs[4];
        #pragma unroll
        for (int i = 0; i < 4; i++) {
            float rm = fmaxf(fmaxf(s[i][0], s[i][1]), fmaxf(s[i][2], s[i][3]));
            #pragma unroll
            for (int o = 1; o < 16; o <<= 1)
                rm = fmaxf(rm, __shfl_xor_sync(0xffffffffu, rm, o, 16));
            float mn = fmaxf(mi[i], rm);
            al[i] = __expf(mi[i] - mn);
            mi[i] = mn;
            float r = 0.0f;
            #pragma unroll
            for (int j = 0; j < 4; j++) {
                float p = __expf(s[i][j] - mn);
                s[i][j] = p;
                r += p;
            }
            #pragma unroll
            for (int o = 1; o < 16; o <<= 1)
                r += __shfl_xor_sync(0xffffffffu, r, o, 16);
            rs[i] = r;
            li[i] = li[i] * al[i] + rs[i];
        }

        #pragma unroll
        for (int i = 0; i < 4; i++)
            #pragma unroll
            for (int j = 0; j < 4; j++)
                Ps[(ty * 4 + i) * 65 + tx * 4 + j] = s[i][j];

        #pragma unroll
        for (int i = 0; i < 4; i++)
            #pragma unroll
            for (int j = 0; j < 4; j++) acc[i][j] *= al[i];

        __syncthreads();

        #pragma unroll 8
        for (int n = 0; n < 64; n++) {
            float p0 = Ps[(ty * 4 + 0) * 65 + n];
            float p1 = Ps[(ty * 4 + 1) * 65 + n];
            float p2 = Ps[(ty * 4 + 2) * 65 + n];
            float p3 = Ps[(ty * 4 + 3) * 65 + n];
            float w0 = Vs[n * 65 + tx * 4 + 0];
            float w1 = Vs[n * 65 + tx * 4 + 1];
            float w2 = Vs[n * 65 + tx * 4 + 2];
            float w3 = Vs[n * 65 + tx * 4 + 3];
            acc[0][0] = fmaf(p0, w0, acc[0][0]); acc[0][1] = fmaf(p0, w1, acc[0][1]);
            acc[0][2] = fmaf(p0, w2, acc[0][2]); acc[0][3] = fmaf(p0, w3, acc[0][3]);
            acc[1][0] = fmaf(p1, w0, acc[1][0]); acc[1][1] = fmaf(p1, w1, acc[1][1]);
            acc[1][2] = fmaf(p1, w2, acc[1][2]); acc[1][3] = fmaf(p1, w3, acc[1][3]);
            acc[2][0] = fmaf(p2, w0, acc[2][0]); acc[2][1] = fmaf(p2, w1, acc[2][1]);
            acc[2][2] = fmaf(p2, w2, acc[2][2]); acc[2][3] = fmaf(p2, w3, acc[2][3]);
            acc[3][0] = fmaf(p3, w0, acc[3][0]); acc[3][1] = fmaf(p3, w1, acc[3][1]);
            acc[3][2] = fmaf(p3, w2, acc[3][2]); acc[3][3] = fmaf(p3, w3, acc[3][3]);
        }
    }

    float* zb = z + ((size_t)bb * SQ + qt * 64) * DM + hh * DH;
    #pragma unroll
    for (int i = 0; i < 4; i++) {
        float inv = 1.0f / li[i];
        #pragma unroll
        for (int j = 0; j < 4; j++)
            zb[(size_t)(ty * 4 + i) * DM + tx * 4 + j] = acc[i][j] * inv;
    }
}

// ---------------- host launcher ---------------------------------------------
static float* sym_addr(const void* symbol) {
    void* p = nullptr;
    cudaGetSymbolAddress(&p, symbol);
    return (float*)p;
}

extern "C" void kernel_launch(void* const* d_in, const int* in_sizes, int n_in,
                              void* d_out, int out_size) {
    const float* resid_pre = (const float*)d_in[0];
    const float* ln1_w = (const float*)d_in[1];
    const float* ln1_b = (const float*)d_in[2];
    const float* W_Q   = (const float*)d_in[3];
    const float* b_Q   = (const float*)d_in[4];
    const float* W_K   = (const float*)d_in[5];
    const float* b_K   = (const float*)d_in[6];
    const float* W_V   = (const float*)d_in[7];
    const float* b_V   = (const float*)d_in[8];
    const float* W_O   = (const float*)d_in[9];
    const float* b_O   = (const float*)d_in[10];
    const float* ln2_w = (const float*)d_in[11];
    const float* ln2_b = (const float*)d_in[12];
    const float* W_in  = (const float*)d_in[13];
    const float* b_in  = (const float*)d_in[14];
    const float* W_out = (const float*)d_in[15];
    const float* b_out = (const float*)d_in[16];
    float* out = (float*)d_out;

    float* xln  = sym_addr(g_xln);
    float* qb   = sym_addr(g_q);
    float* kb   = sym_addr(g_k);
    float* vb   = sym_addr(g_v);
    float* zb   = sym_addr(g_z);
    float* rmid = sym_addr(g_rmid);
    float* h2   = sym_addr(g_h2);
    float* act  = sym_addr(g_act);
    float* wq   = sym_addr(g_wq);
    float* wk   = sym_addr(g_wk);
    float* wv   = sym_addr(g_wv);

    // 1. repack QKV weights
    repack_kernel<<<(DM * DM) / 256, 256>>>(W_Q, W_K, W_V);

    // 2. LN1
    ln_kernel<<<NTOK, 256>>>(resid_pre, ln1_w, ln1_b, xln);

    // 3. QKV projections (tensor cores, scatter epilogue into [b,h,s,dh])
    dim3 gq(DM / 128, NTOK / 128);
    hgemm_kernel<1><<<gq, 256>>>(xln, wq, b_Q, nullptr, qb, NTOK, DM, DM);
    hgemm_kernel<1><<<gq, 256>>>(xln, wk, b_K, nullptr, kb, NTOK, DM, DM);
    hgemm_kernel<1><<<gq, 256>>>(xln, wv, b_V, nullptr, vb, NTOK, DM, DM);

    // 4. flash attention
    static const size_t fl_smem = 4 * 64 * 65 * sizeof(float);  // 66560
    cudaFuncSetAttribute(flash_kernel,
                         cudaFuncAttributeMaxDynamicSharedMemorySize, (int)fl_smem);
    flash_kernel<<<dim3(SQ / 64, BT * NH), 256, fl_smem>>>(qb, kb, vb, zb);

    // 5. O-proj + residual -> resid_mid
    hgemm_kernel<2><<<gq, 256>>>(zb, W_O, b_O, resid_pre, rmid, NTOK, DM, DM);

    // 6. LN2
    ln_kernel<<<NTOK, 256>>>(rmid, ln2_w, ln2_b, h2);

    // 7. MLP in + ReLU
    dim3 gi(DMLP / 128, NTOK / 128);
    hgemm_kernel<3><<<gi, 256>>>(h2, W_in, b_in, nullptr, act, NTOK, DMLP, DM);

    // 8. MLP out + bias + residual -> output
    hgemm_kernel<2><<<gq, 256>>>(act, W_out, b_out, rmid, out, NTOK, DM, DMLP);
}

// round 9
// speedup vs baseline: 2.8918x; 1.4384x over previous
#include <cuda_runtime.h>
#include <cuda_bf16.h>
#include <stdint.h>
#include <cstdint>
#include <math.h>

// Problem constants
#define SQ   2048
#define DM   1024
#define NH   16
#define DH   64
#define BT   2
#define NTOK (BT*SQ)      // 4096
#define DMLP 4096

// ---------------- scratch (device globals; no allocations allowed) ----------
__device__ float g_xln [NTOK*DM];
__device__ float g_q   [NTOK*DM];      // [B,H,S,DH]
__device__ float g_k   [NTOK*DM];
__device__ float g_v   [NTOK*DM];
__device__ float g_z   [NTOK*DM];      // attn concat [tok, h*64+dh]
__device__ float g_rmid[NTOK*DM];
__device__ float g_h2  [NTOK*DM];
__device__ float g_act [NTOK*DMLP];
__device__ float g_wq  [DM*DM];        // repacked [d, h*64+k]
__device__ float g_wk  [DM*DM];
__device__ float g_wv  [DM*DM];

// ---------------- weight repack: [h,d,k] -> [d, h*64+k] ---------------------
__global__ void repack_kernel(const float* __restrict__ wq,
                              const float* __restrict__ wk,
                              const float* __restrict__ wv) {
    int idx = blockIdx.x * 256 + threadIdx.x;
    int d  = idx >> 10;
    int n  = idx & 1023;
    int h  = n >> 6;
    int kk = n & 63;
    int src = h * (DM * DH) + d * DH + kk;
    g_wq[idx] = wq[src];
    g_wk[idx] = wk[src];
    g_wv[idx] = wv[src];
}

// ---------------- layernorm: one block per row (1024 elems, 256 thr) --------
__global__ void ln_kernel(const float* __restrict__ x, const float* __restrict__ w,
                          const float* __restrict__ b, float* __restrict__ y) {
    int row = blockIdx.x;
    int t = threadIdx.x;
    const float4 xv = *(const float4*)(x + (size_t)row * DM + t * 4);
    float s  = xv.x + xv.y + xv.z + xv.w;
    float ss = xv.x*xv.x + xv.y*xv.y + xv.z*xv.z + xv.w*xv.w;
    #pragma unroll
    for (int o = 16; o; o >>= 1) {
        s  += __shfl_xor_sync(0xffffffffu, s,  o);
        ss += __shfl_xor_sync(0xffffffffu, ss, o);
    }
    __shared__ float sb[8], sb2[8];
    int wid = t >> 5, lane = t & 31;
    if (lane == 0) { sb[wid] = s; sb2[wid] = ss; }
    __syncthreads();
    if (wid == 0) {
        s  = sb[lane & 7];
        ss = sb2[lane & 7];
        #pragma unroll
        for (int o = 4; o; o >>= 1) {
            s  += __shfl_xor_sync(0xffffffffu, s,  o);
            ss += __shfl_xor_sync(0xffffffffu, ss, o);
        }
        if (lane == 0) { sb[0] = s; sb2[0] = ss; }
    }
    __syncthreads();
    float mean = sb[0] * (1.0f / DM);
    float var  = sb2[0] * (1.0f / DM) - mean * mean;
    float rstd = rsqrtf(var + 1e-5f);
    float4 wv4 = *(const float4*)(w + t * 4);
    float4 bv4 = *(const float4*)(b + t * 4);
    float4 o4;
    o4.x = (xv.x - mean) * rstd * wv4.x + bv4.x;
    o4.y = (xv.y - mean) * rstd * wv4.y + bv4.y;
    o4.z = (xv.z - mean) * rstd * wv4.z + bv4.z;
    o4.w = (xv.w - mean) * rstd * wv4.w + bv4.w;
    *(float4*)(y + (size_t)row * DM + t * 4) = o4;
}

// ---------------- mma helpers ------------------------------------------------
__device__ __forceinline__ uint32_t smem_u32(const void* p) {
    return (uint32_t)__cvta_generic_to_shared(p);
}

#define LDSM_X4(r0,r1,r2,r3,addr) \
    asm volatile("ldmatrix.sync.aligned.m8n8.x4.shared.b16 {%0,%1,%2,%3}, [%4];" \
        : "=r"(r0),"=r"(r1),"=r"(r2),"=r"(r3) : "r"(addr))

#define LDSM_X4_T(r0,r1,r2,r3,addr) \
    asm volatile("ldmatrix.sync.aligned.m8n8.x4.trans.shared.b16 {%0,%1,%2,%3}, [%4];" \
        : "=r"(r0),"=r"(r1),"=r"(r2),"=r"(r3) : "r"(addr))

#define MMA16816(c, a0,a1,a2,a3, b0,b1) \
    asm volatile("mma.sync.aligned.m16n8k16.row.col.f32.bf16.bf16.f32 " \
        "{%0,%1,%2,%3}, {%4,%5,%6,%7}, {%8,%9}, {%0,%1,%2,%3};" \
        : "+f"(c[0]),"+f"(c[1]),"+f"(c[2]),"+f"(c[3]) \
        : "r"(a0),"r"(a1),"r"(a2),"r"(a3), "r"(b0),"r"(b1))

__device__ __forceinline__ uint32_t pack_bf2(float a, float b) {
    __nv_bfloat162 t = __floats2bfloat162_rn(a, b);
    return *reinterpret_cast<uint32_t*>(&t);
}

// ---------------- tensor-core GEMM: bf16 hi/lo split, m16n8k16 mma ----------
#define APAD 40
#define BPAD 136

template <int MODE>
__global__ __launch_bounds__(256, 2)
void hgemm_kernel(const float* __restrict__ A, const float* __restrict__ B,
                  const float* __restrict__ bias, const float* __restrict__ R,
                  float* __restrict__ C, int M, int N, int K) {
    __shared__ __align__(16) __nv_bfloat16 As[2][128][APAD];   // [hi/lo][m][k]
    __shared__ __align__(16) __nv_bfloat16 Bs[2][32][BPAD];    // [hi/lo][k][n]

    int tid = threadIdx.x;
    int lane = tid & 31;
    int warp = tid >> 5;
    int wm = warp >> 2;        // 0..1
    int wn = warp & 3;         // 0..3
    int m0 = blockIdx.y * 128, n0 = blockIdx.x * 128;

    int ar = tid >> 3;         // 0..31  (A row base)
    int ac = (tid & 7) * 4;    // A k-col (float4)
    int br = tid >> 5;         // 0..7   (B k-row base)
    int bc = (tid & 31) * 4;   // B n-col (float4)

    float acc[4][4][4];
    #pragma unroll
    for (int i = 0; i < 4; i++)
        #pragma unroll
        for (int j = 0; j < 4; j++)
            #pragma unroll
            for (int c = 0; c < 4; c++) acc[i][j][c] = 0.0f;

    uint32_t a_base_hi = smem_u32(&As[0][wm*64 + (lane & 15)][(lane >> 4) * 8]);
    uint32_t a_base_lo = smem_u32(&As[1][wm*64 + (lane & 15)][(lane >> 4) * 8]);
    uint32_t b_base_hi = smem_u32(&Bs[0][lane & 15][wn*32 + (lane >> 4) * 8]);
    uint32_t b_base_lo = smem_u32(&Bs[1][lane & 15][wn*32 + (lane >> 4) * 8]);

    for (int k0 = 0; k0 < K; k0 += 32) {
        #pragma unroll
        for (int q = 0; q < 4; q++) {
            int r = ar + q * 32;
            const float4 av = *(const float4*)(A + (size_t)(m0 + r) * K + k0 + ac);
            float f[4] = {av.x, av.y, av.z, av.w};
            #pragma unroll
            for (int e = 0; e < 4; e++) {
                __nv_bfloat16 h = __float2bfloat16(f[e]);
                As[0][r][ac + e] = h;
                As[1][r][ac + e] = __float2bfloat16(f[e] - __bfloat162float(h));
            }
        }
        #pragma unroll
        for (int q = 0; q < 4; q++) {
            int r = br + q * 8;
            const float4 bv = *(const float4*)(B + (size_t)(k0 + r) * N + n0 + bc);
            float f[4] = {bv.x, bv.y, bv.z, bv.w};
            #pragma unroll
            for (int e = 0; e < 4; e++) {
                __nv_bfloat16 h = __float2bfloat16(f[e]);
                Bs[0][r][bc + e] = h;
                Bs[1][r][bc + e] = __float2bfloat16(f[e] - __bfloat162float(h));
            }
        }
        __syncthreads();

        #pragma unroll
        for (int ks = 0; ks < 2; ks++) {
            uint32_t bh[8], bl[8];
            {
                uint32_t off = (uint32_t)(ks * 16 * BPAD * 2);
                LDSM_X4_T(bh[0], bh[1], bh[2], bh[3], b_base_hi + off);
                LDSM_X4_T(bh[4], bh[5], bh[6], bh[7], b_base_hi + off + 16 * 2);
                LDSM_X4_T(bl[0], bl[1], bl[2], bl[3], b_base_lo + off);
                LDSM_X4_T(bl[4], bl[5], bl[6], bl[7], b_base_lo + off + 16 * 2);
            }
            #pragma unroll
            for (int i = 0; i < 4; i++) {
                uint32_t ah0, ah1, ah2, ah3, al0, al1, al2, al3;
                uint32_t aoff = (uint32_t)((i * 16 * APAD + ks * 16) * 2);
                LDSM_X4(ah0, ah1, ah2, ah3, a_base_hi + aoff);
                LDSM_X4(al0, al1, al2, al3, a_base_lo + aoff);
                #pragma unroll
                for (int j = 0; j < 4; j++) {
                    MMA16816(acc[i][j], ah0, ah1, ah2, ah3, bh[2*j], bh[2*j+1]);
                    MMA16816(acc[i][j], ah0, ah1, ah2, ah3, bl[2*j], bl[2*j+1]);
                    MMA16816(acc[i][j], al0, al1, al2, al3, bh[2*j], bh[2*j+1]);
                }
            }
        }
        __syncthreads();
    }

    int gid = lane >> 2;
    int tid4 = lane & 3;
    #pragma unroll
    for (int i = 0; i < 4; i++) {
        #pragma unroll
        for (int j = 0; j < 4; j++) {
            #pragma unroll
            for (int c = 0; c < 4; c++) {
                int m = m0 + wm * 64 + i * 16 + gid + (c >> 1) * 8;
                int n = n0 + wn * 32 + j * 8 + tid4 * 2 + (c & 1);
                float val = acc[i][j][c] + bias[n];
                if (MODE == 0) {
                    C[(size_t)m * N + n] = val;
                } else if (MODE == 1) {
                    int bb = m >> 11;
                    int s  = m & (SQ - 1);
                    int h  = n >> 6;
                    int dk = n & 63;
                    C[(((size_t)(bb * NH + h)) * SQ + s) * DH + dk] = val;
                } else if (MODE == 2) {
                    C[(size_t)m * N + n] = val + R[(size_t)m * N + n];
                } else {
                    C[(size_t)m * N + n] = fmaxf(val, 0.0f);
                }
            }
        }
    }
}

// ---------------- tensor-core flash attention --------------------------------
// q,k,v: [B,H,S,DH] fp32. Out z: [tok, h*64+dh] fp32.
// CTA: 128 Q rows, 8 warps (16 rows each). K/V tiles of 64 keys.
// QK^T: bf16 hi/lo, 3 passes (fp32-class scores). P*V: P bf16, V hi/lo, 2 passes.
#define FBM 128
#define FBN 64
#define FPITCH 72

__global__ __launch_bounds__(256, 1)
void flashmma_kernel(const float* __restrict__ q, const float* __restrict__ k,
                     const float* __restrict__ v, float* __restrict__ z) {
    extern __shared__ __nv_bfloat16 fsm[];
    __nv_bfloat16* Qh = fsm;                       // [128][72]
    __nv_bfloat16* Ql = Qh + FBM * FPITCH;
    __nv_bfloat16* Kh = Ql + FBM * FPITCH;         // [64][72]
    __nv_bfloat16* Kl = Kh + FBN * FPITCH;
    __nv_bfloat16* Vh = Kl + FBN * FPITCH;         // [64][72]
    __nv_bfloat16* Vl = Vh + FBN * FPITCH;

    int qt = blockIdx.x, bh = blockIdx.y;
    int bb = bh >> 4, hh = bh & 15;
    int tid = threadIdx.x, lane = tid & 31, w = tid >> 5;
    int gid = lane >> 2, qd = lane & 3;

    const float* qbase = q + ((size_t)bh * SQ + (size_t)qt * FBM) * DH;
    const float* kbase = k + (size_t)bh * SQ * DH;
    const float* vbase = v + (size_t)bh * SQ * DH;

    // ---- stage Q (128x64 fp32 -> bf16 hi/lo) ----
    #pragma unroll
    for (int j = 0; j < 8; j++) {
        int idx = tid + j * 256;          // 0..2047 float4s
        int r = idx >> 4, c = (idx & 15) * 4;
        float4 t4 = *(const float4*)(qbase + (size_t)r * DH + c);
        float f[4] = {t4.x, t4.y, t4.z, t4.w};
        #pragma unroll
        for (int e = 0; e < 4; e++) {
            __nv_bfloat16 h = __float2bfloat16(f[e]);
            Qh[r * FPITCH + c + e] = h;
            Ql[r * FPITCH + c + e] = __float2bfloat16(f[e] - __bfloat162float(h));
        }
    }
    __syncthreads();

    // ---- Q fragments (persist in registers) ----
    uint32_t qh[4][4], ql[4][4];
    #pragma unroll
    for (int kc = 0; kc < 4; kc++) {
        uint32_t a1 = smem_u32(&Qh[(w * 16 + (lane & 15)) * FPITCH + kc * 16 + (lane >> 4) * 8]);
        LDSM_X4(qh[kc][0], qh[kc][1], qh[kc][2], qh[kc][3], a1);
        uint32_t a2 = smem_u32(&Ql[(w * 16 + (lane & 15)) * FPITCH + kc * 16 + (lane >> 4) * 8]);
        LDSM_X4(ql[kc][0], ql[kc][1], ql[kc][2], ql[kc][3], a2);
    }

    float o[8][4];
    #pragma unroll
    for (int j = 0; j < 8; j++)
        #pragma unroll
        for (int c = 0; c < 4; c++) o[j][c] = 0.0f;
    float mi0 = -1e30f, mi1 = -1e30f, li0 = 0.0f, li1 = 0.0f;

    int row0g = qt * FBM + w * 16 + gid;     // global row of acc slots 0,1
    int row1g = row0g + 8;                   // global row of acc slots 2,3

    int nkt = 2 * qt + 2;
    for (int kt = 0; kt < nkt; kt++) {
        __syncthreads();
        // ---- stage K,V tile (64x64 each) ----
        #pragma unroll
        for (int j = 0; j < 4; j++) {
            int idx = tid + j * 256;          // 0..1023 float4s
            int r = idx >> 4, c = (idx & 15) * 4;
            const float* kp = kbase + ((size_t)kt * FBN + r) * DH + c;
            float4 t4 = *(const float4*)kp;
            float f[4] = {t4.x, t4.y, t4.z, t4.w};
            #pragma unroll
            for (int e = 0; e < 4; e++) {
                __nv_bfloat16 h = __float2bfloat16(f[e]);
                Kh[r * FPITCH + c + e] = h;
                Kl[r * FPITCH + c + e] = __float2bfloat16(f[e] - __bfloat162float(h));
            }
            const float* vp = vbase + ((size_t)kt * FBN + r) * DH + c;
            float4 u4 = *(const float4*)vp;
            float g[4] = {u4.x, u4.y, u4.z, u4.w};
            #pragma unroll
            for (int e = 0; e < 4; e++) {
                __nv_bfloat16 h = __float2bfloat16(g[e]);
                Vh[r * FPITCH + c + e] = h;
                Vl[r * FPITCH + c + e] = __float2bfloat16(g[e] - __bfloat162float(h));
            }
        }
        __syncthreads();

        // ---- S = Q K^T (3-pass hi/lo) ----
        float s[8][4];
        #pragma unroll
        for (int j = 0; j < 8; j++)
            #pragma unroll
            for (int c = 0; c < 4; c++) s[j][c] = 0.0f;

        #pragma unroll
        for (int kc = 0; kc < 4; kc++) {
            #pragma unroll
            for (int jj = 0; jj < 4; jj++) {
                // non-trans ldmatrix from K[key][d]: tiles 2jj, 2jj+1
                uint32_t addr_h = smem_u32(&Kh[((jj * 2 + (lane >> 4)) * 8 + (lane & 7)) * FPITCH
                                               + kc * 16 + ((lane >> 3) & 1) * 8]);
                uint32_t addr_l = smem_u32(&Kl[((jj * 2 + (lane >> 4)) * 8 + (lane & 7)) * FPITCH
                                               + kc * 16 + ((lane >> 3) & 1) * 8]);
                uint32_t kh0, kh1, kh2, kh3, kl0, kl1, kl2, kl3;
                LDSM_X4(kh0, kh1, kh2, kh3, addr_h);
                LDSM_X4(kl0, kl1, kl2, kl3, addr_l);
                MMA16816(s[jj*2  ], qh[kc][0], qh[kc][1], qh[kc][2], qh[kc][3], kh0, kh1);
                MMA16816(s[jj*2  ], qh[kc][0], qh[kc][1], qh[kc][2], qh[kc][3], kl0, kl1);
                MMA16816(s[jj*2  ], ql[kc][0], ql[kc][1], ql[kc][2], ql[kc][3], kh0, kh1);
                MMA16816(s[jj*2+1], qh[kc][0], qh[kc][1], qh[kc][2], qh[kc][3], kh2, kh3);
                MMA16816(s[jj*2+1], qh[kc][0], qh[kc][1], qh[kc][2], qh[kc][3], kl2, kl3);
                MMA16816(s[jj*2+1], ql[kc][0], ql[kc][1], ql[kc][2], ql[kc][3], kh2, kh3);
            }
        }

        // ---- scale + causal mask ----
        #pragma unroll
        for (int j = 0; j < 8; j++)
            #pragma unroll
            for (int c = 0; c < 4; c++) s[j][c] *= 0.125f;

        if (kt * 64 + 63 > qt * 128 + w * 16) {
            #pragma unroll
            for (int j = 0; j < 8; j++) {
                int col = kt * 64 + j * 8 + qd * 2;
                if (col     > row0g) s[j][0] = -1e30f;
                if (col + 1 > row0g) s[j][1] = -1e30f;
                if (col     > row1g) s[j][2] = -1e30f;
                if (col + 1 > row1g) s[j][3] = -1e30f;
            }
        }

        // ---- online softmax (rows gid / gid+8) ----
        float rm0 = -1e30f, rm1 = -1e30f;
        #pragma unroll
        for (int j = 0; j < 8; j++) {
            rm0 = fmaxf(rm0, fmaxf(s[j][0], s[j][1]));
            rm1 = fmaxf(rm1, fmaxf(s[j][2], s[j][3]));
        }
        rm0 = fmaxf(rm0, __shfl_xor_sync(0xffffffffu, rm0, 1));
        rm0 = fmaxf(rm0, __shfl_xor_sync(0xffffffffu, rm0, 2));
        rm1 = fmaxf(rm1, __shfl_xor_sync(0xffffffffu, rm1, 1));
        rm1 = fmaxf(rm1, __shfl_xor_sync(0xffffffffu, rm1, 2));
        float mn0 = fmaxf(mi0, rm0), mn1 = fmaxf(mi1, rm1);
        float al0 = __expf(mi0 - mn0), al1 = __expf(mi1 - mn1);
        mi0 = mn0; mi1 = mn1;
        float rs0 = 0.0f, rs1 = 0.0f;
        #pragma unroll
        for (int j = 0; j < 8; j++) {
            s[j][0] = __expf(s[j][0] - mn0);
            s[j][1] = __expf(s[j][1] - mn0);
            s[j][2] = __expf(s[j][2] - mn1);
            s[j][3] = __expf(s[j][3] - mn1);
            rs0 += s[j][0] + s[j][1];
            rs1 += s[j][2] + s[j][3];
        }
        rs0 += __shfl_xor_sync(0xffffffffu, rs0, 1);
        rs0 += __shfl_xor_sync(0xffffffffu, rs0, 2);
        rs1 += __shfl_xor_sync(0xffffffffu, rs1, 1);
        rs1 += __shfl_xor_sync(0xffffffffu, rs1, 2);
        li0 = li0 * al0 + rs0;
        li1 = li1 * al1 + rs1;

        #pragma unroll
        for (int j = 0; j < 8; j++) {
            o[j][0] *= al0; o[j][1] *= al0;
            o[j][2] *= al1; o[j][3] *= al1;
        }

        // ---- pack P into A-operand fragments ----
        uint32_t pa[4][4];
        #pragma unroll
        for (int kc = 0; kc < 4; kc++) {
            pa[kc][0] = pack_bf2(s[2*kc  ][0], s[2*kc  ][1]);
            pa[kc][1] = pack_bf2(s[2*kc  ][2], s[2*kc  ][3]);
            pa[kc][2] = pack_bf2(s[2*kc+1][0], s[2*kc+1][1]);
            pa[kc][3] = pack_bf2(s[2*kc+1][2], s[2*kc+1][3]);
        }

        // ---- O += P V (2-pass: V hi + V lo) ----
        #pragma unroll
        for (int kc = 0; kc < 4; kc++) {
            #pragma unroll
            for (int jj = 0; jj < 4; jj++) {
                // trans ldmatrix from V[key][dh]: dh-tiles 2jj, 2jj+1, key-chunk kc
                uint32_t addr_h = smem_u32(&Vh[(kc * 16 + (lane & 7) + ((lane >> 3) & 1) * 8) * FPITCH
                                               + (jj * 2 + (lane >> 4)) * 8]);
                uint32_t addr_l = smem_u32(&Vl[(kc * 16 + (lane & 7) + ((lane >> 3) & 1) * 8) * FPITCH
                                               + (jj * 2 + (lane >> 4)) * 8]);
                uint32_t vh0, vh1, vh2, vh3, vl0, vl1, vl2, vl3;
                LDSM_X4_T(vh0, vh1, vh2, vh3, addr_h);
                LDSM_X4_T(vl0, vl1, vl2, vl3, addr_l);
                MMA16816(o[jj*2  ], pa[kc][0], pa[kc][1], pa[kc][2], pa[kc][3], vh0, vh1);
                MMA16816(o[jj*2  ], pa[kc][0], pa[kc][1], pa[kc][2], pa[kc][3], vl0, vl1);
                MMA16816(o[jj*2+1], pa[kc][0], pa[kc][1], pa[kc][2], pa[kc][3], vh2, vh3);
                MMA16816(o[jj*2+1], pa[kc][0], pa[kc][1], pa[kc][2], pa[kc][3], vl2, vl3);
            }
        }
    }

    // ---- write z [tok, h*64+dh] ----
    float inv0 = 1.0f / li0, inv1 = 1.0f / li1;
    float* zb = z + ((size_t)bb * SQ + (size_t)qt * FBM + w * 16) * DM + hh * DH;
    #pragma unroll
    for (int j = 0; j < 8; j++) {
        int col = j * 8 + qd * 2;
        *(float2*)(zb + (size_t)gid * DM + col)       = make_float2(o[j][0] * inv0, o[j][1] * inv0);
        *(float2*)(zb + (size_t)(gid + 8) * DM + col) = make_float2(o[j][2] * inv1, o[j][3] * inv1);
    }
}

// ---------------- host launcher ---------------------------------------------
static float* sym_addr(const void* symbol) {
    void* p = nullptr;
    cudaGetSymbolAddress(&p, symbol);
    return (float*)p;
}

extern "C" void kernel_launch(void* const* d_in, const int* in_sizes, int n_in,
                              void* d_out, int out_size) {
    const float* resid_pre = (const float*)d_in[0];
    const float* ln1_w = (const float*)d_in[1];
    const float* ln1_b = (const float*)d_in[2];
    const float* W_Q   = (const float*)d_in[3];
    const float* b_Q   = (const float*)d_in[4];
    const float* W_K   = (const float*)d_in[5];
    const float* b_K   = (const float*)d_in[6];
    const float* W_V   = (const float*)d_in[7];
    const float* b_V   = (const float*)d_in[8];
    const float* W_O   = (const float*)d_in[9];
    const float* b_O   = (const float*)d_in[10];
    const float* ln2_w = (const float*)d_in[11];
    const float* ln2_b = (const float*)d_in[12];
    const float* W_in  = (const float*)d_in[13];
    const float* b_in  = (const float*)d_in[14];
    const float* W_out = (const float*)d_in[15];
    const float* b_out = (const float*)d_in[16];
    float* out = (float*)d_out;

    float* xln  = sym_addr(g_xln);
    float* qb   = sym_addr(g_q);
    float* kb   = sym_addr(g_k);
    float* vb   = sym_addr(g_v);
    float* zb   = sym_addr(g_z);
    float* rmid = sym_addr(g_rmid);
    float* h2   = sym_addr(g_h2);
    float* act  = sym_addr(g_act);
    float* wq   = sym_addr(g_wq);
    float* wk   = sym_addr(g_wk);
    float* wv   = sym_addr(g_wv);

    // 1. repack QKV weights
    repack_kernel<<<(DM * DM) / 256, 256>>>(W_Q, W_K, W_V);

    // 2. LN1
    ln_kernel<<<NTOK, 256>>>(resid_pre, ln1_w, ln1_b, xln);

    // 3. QKV projections (tensor cores, scatter epilogue into [b,h,s,dh])
    dim3 gq(DM / 128, NTOK / 128);
    hgemm_kernel<1><<<gq, 256>>>(xln, wq, b_Q, nullptr, qb, NTOK, DM, DM);
    hgemm_kernel<1><<<gq, 256>>>(xln, wk, b_K, nullptr, kb, NTOK, DM, DM);
    hgemm_kernel<1><<<gq, 256>>>(xln, wv, b_V, nullptr, vb, NTOK, DM, DM);

    // 4. tensor-core flash attention
    const size_t fl_smem = (size_t)(2*FBM + 4*FBN) * FPITCH * sizeof(__nv_bfloat16); // 73728
    cudaFuncSetAttribute(flashmma_kernel,
                         cudaFuncAttributeMaxDynamicSharedMemorySize, (int)fl_smem);
    flashmma_kernel<<<dim3(SQ / FBM, BT * NH), 256, fl_smem>>>(qb, kb, vb, zb);

    // 5. O-proj + residual -> resid_mid
    hgemm_kernel<2><<<gq, 256>>>(zb, W_O, b_O, resid_pre, rmid, NTOK, DM, DM);

    // 6. LN2
    ln_kernel<<<NTOK, 256>>>(rmid, ln2_w, ln2_b, h2);

    // 7. MLP in + ReLU
    dim3 gi(DMLP / 128, NTOK / 128);
    hgemm_kernel<3><<<gi, 256>>>(h2, W_in, b_in, nullptr, act, NTOK, DMLP, DM);

    // 8. MLP out + bias + residual -> output
    hgemm_kernel<2><<<gq, 256>>>(act, W_out, b_out, rmid, out, NTOK, DM, DMLP);
}